// round 10
// baseline (speedup 1.0000x reference)
#include <cuda_runtime.h>
#include <math.h>

#define Nn 128
#define C  2048
#define L  512
#define TT 512

// -------- scratch (device globals; no allocations allowed) --------
__device__ float g_theta[Nn*L];
__device__ float g_v[Nn*C];
__device__ float g_lat[Nn*L];
__device__ float g_part[16*Nn*L > 4*Nn*C ? 16*Nn*L : 4*Nn*C];  // split-K partials

// ---- helpers ----
__device__ __forceinline__ unsigned long long pack2(float a, float b) {
    unsigned long long r;
    asm("mov.b64 %0, {%1, %2};" : "=l"(r) : "r"(__float_as_uint(a)), "r"(__float_as_uint(b)));
    return r;
}
__device__ __forceinline__ void ffma2(unsigned long long& d, unsigned long long a, unsigned long long b) {
    asm("fma.rn.f32x2 %0, %1, %2, %0;" : "+l"(d) : "l"(a), "l"(b));
}
__device__ __forceinline__ unsigned smem_u32(const void* p) {
    return (unsigned)__cvta_generic_to_shared(p);
}
__device__ __forceinline__ unsigned mapa_peer(unsigned localAddr, unsigned peer) {
    unsigned r;
    asm("mapa.shared::cluster.u32 %0, %1, %2;" : "=r"(r) : "r"(localAddr), "r"(peer));
    return r;
}

// ============ projection: packed-f32x2, CTA = 128 oc x 64 n, split-K ============
template<bool WT>
__global__ __launch_bounds__(256) void proj2_kernel(
    const float* __restrict__ act, const float* __restrict__ w,
    float* __restrict__ part, int K, int O, int kchunk)
{
    __shared__ float ws[32*132];
    __shared__ float th[64*36];
    const int tid = threadIdx.x;
    const int lane = tid & 31;
    const int wid = tid >> 5;
    const int ocbase = blockIdx.x * 128;
    const int nbase  = blockIdx.y * 64;
    const int sidx   = blockIdx.z;
    const int k0 = sidx * kchunk;

    unsigned long long acc[2][8];
#pragma unroll
    for (int p = 0; p < 2; p++)
#pragma unroll
        for (int j = 0; j < 8; j++) acc[p][j] = 0ull;

    for (int kb = k0; kb < k0 + kchunk; kb += 32) {
#pragma unroll
        for (int j = 0; j < 2; j++) {
            int f = tid + 256*j;
            int n = f >> 3;
            int kq = (f & 7) << 2;
            float4 v4 = *(const float4*)(act + (size_t)(nbase+n)*K + kb + kq);
            *(float4*)(th + n*36 + kq) = v4;
        }
        if (WT) {
#pragma unroll
            for (int j = 0; j < 4; j++) {
                int f = tid + 256*j;
                int kk = f >> 5;
                int oq = (f & 31) << 2;
                float4 v4 = *(const float4*)(w + (size_t)(kb+kk)*O + ocbase + oq);
                *(float4*)(ws + kk*132 + oq) = v4;
            }
        } else {
#pragma unroll
            for (int j = 0; j < 4; j++) {
                int f = tid + 256*j;
                int o = f >> 3;
                int kq = (f & 7) << 2;
                float4 v4 = *(const float4*)(w + (size_t)(ocbase+o)*K + kb + kq);
                ws[(kq+0)*132 + o] = v4.x;
                ws[(kq+1)*132 + o] = v4.y;
                ws[(kq+2)*132 + o] = v4.z;
                ws[(kq+3)*132 + o] = v4.w;
            }
        }
        __syncthreads();
        const float* tp = th + wid*8*36;
#pragma unroll 4
        for (int kk = 0; kk < 32; kk++) {
            float2 w0 = *(const float2*)(ws + kk*132 + 2*lane);
            float2 w1 = *(const float2*)(ws + kk*132 + 64 + 2*lane);
            unsigned long long wp0 = pack2(w0.x, w0.y);
            unsigned long long wp1 = pack2(w1.x, w1.y);
#pragma unroll
            for (int j = 0; j < 8; j++) {
                float t = tp[j*36 + kk];
                unsigned long long t2 = pack2(t, t);
                ffma2(acc[0][j], wp0, t2);
                ffma2(acc[1][j], wp1, t2);
            }
        }
        __syncthreads();
    }
#pragma unroll
    for (int j = 0; j < 8; j++) {
        int n = nbase + wid*8 + j;
        float* dst = part + ((size_t)sidx*Nn + n)*O + ocbase;
        *(float2*)(dst + 2*lane)      = *(float2*)&acc[0][j];
        *(float2*)(dst + 64 + 2*lane) = *(float2*)&acc[1][j];
    }
}

// ============ deterministic split-K reduce + bias, float4 ============
__global__ __launch_bounds__(128) void reduce4_kernel(
    const float* __restrict__ part, float* __restrict__ dst,
    const float* __restrict__ bias, int S, int omask, int total)
{
    int i4 = (blockIdx.x*blockDim.x + threadIdx.x) * 4;
    if (i4 >= total) return;
    float4 a = make_float4(0.f, 0.f, 0.f, 0.f);
    for (int s = 0; s < S; s++) {
        float4 p = *(const float4*)(part + (size_t)s*total + i4);
        a.x += p.x; a.y += p.y; a.z += p.z; a.w += p.w;
    }
    if (bias) {
        float4 b = *(const float4*)(bias + (i4 & omask));
        a.x += b.x; a.y += b.y; a.z += b.z; a.w += b.w;
    }
    *(float4*)(dst + i4) = a;
}

// ============ attn v7: cluster(2) channel-split, 2 CTAs/SM, 16-t chunks ============
// Cluster = 2 CTAs for one n, each owns 1024 channels, streams all 512 t.
// CTA: 256 threads / 8 warps; warp w owns channels r*1024 + [w*128, +128).
// Lane: cg = lane>>2 (8 channel subs), tq = lane&3 (t-quad of the 16-t chunk).
// Thread channel i (0..15): c = r*1024 + w*128 + i*8 + cg; x[i] = 4 t at tq*4.
// Score partials pushed to BOTH CTAs' smem (st.shared::cluster); the remote
// arrive is RELEASE.CLUSTER so the acquire.cluster wait observes the pushed
// data (R9 bug: default .release.cta arrive -> stale sp reads, rel_err 4.6e-3).
__global__ __launch_bounds__(256, 2) __cluster_dims__(2, 1, 1)
void attn7_kernel(const float* __restrict__ lt, const float* __restrict__ upart,
                  float* __restrict__ v)
{
    __shared__ float4 sp[2][16][4];                 // [buf][src warp 0..15][tq]
    __shared__ __align__(8) unsigned long long mbar[2];

    const int n = blockIdx.x >> 1;
    unsigned r;
    asm("mov.u32 %0, %%cluster_ctarank;" : "=r"(r));
    const unsigned peer = r ^ 1u;

    const int tid = threadIdx.x;
    const int lane = tid & 31;
    const int w = tid >> 5;                         // 8 warps
    const int cg = lane >> 2;
    const int tq = lane & 3;
    const int cbase = (int)r*1024 + w*128 + cg;     // + i*8

    const float* ltn = lt + (size_t)n*C*TT + (size_t)cbase*TT + tq*4;

    if (tid < 2) {
        unsigned a = smem_u32(&mbar[tid]);
        asm volatile("mbarrier.init.shared.b64 [%0], 64;" :: "r"(a) : "memory");
    }
    // peer's mbar init must be visible before any cluster arrival
    asm volatile("barrier.cluster.arrive.aligned;" ::: "memory");
    asm volatile("barrier.cluster.wait.aligned;" ::: "memory");

    // fused split-K reduce of u (S=4 partials)
    float ur[16];
    float vac[16];
#pragma unroll
    for (int i = 0; i < 16; i++) {
        float a = 0.f;
#pragma unroll
        for (int s = 0; s < 4; s++)
            a += upart[(size_t)s*Nn*C + n*C + cbase + i*8];
        ur[i] = a;
        vac[i] = 0.f;
    }
    float s_run = 0.f;

    // precomputed sync addresses (lanes 0..3 store slot [w][lane] local, [8+w][lane] remote)
    unsigned loc_sp0 = smem_u32(&sp[0][8 + w][lane & 3]);
    unsigned rem_sp0 = mapa_peer(loc_sp0, peer);
    unsigned loc_mb0 = smem_u32(&mbar[0]);
    unsigned rem_mb0 = mapa_peer(loc_mb0, peer);

    for (int ch = 0; ch < 32; ch++) {
        const int buf = ch & 1;
        const int ph  = (ch >> 1) & 1;

        // ---- load 16-t chunk into registers (16 LDG.128) ----
        float4 x[16];
#pragma unroll
        for (int i = 0; i < 16; i++)
            x[i] = *(const float4*)(ltn + (size_t)i*8*TT + ch*16);

        // ---- score partial for this CTA's 1024 channels, 4 t values ----
        float4 s4 = make_float4(0.f, 0.f, 0.f, 0.f);
#pragma unroll
        for (int i = 0; i < 16; i++) {
            s4.x += ur[i]*x[i].x; s4.y += ur[i]*x[i].y;
            s4.z += ur[i]*x[i].z; s4.w += ur[i]*x[i].w;
        }
#pragma unroll
        for (int off = 4; off <= 16; off <<= 1) {
            s4.x += __shfl_xor_sync(~0u, s4.x, off);
            s4.y += __shfl_xor_sync(~0u, s4.y, off);
            s4.z += __shfl_xor_sync(~0u, s4.z, off);
            s4.w += __shfl_xor_sync(~0u, s4.w, off);
        }

        if (lane < 4) {
            // local slot [w][lane]
            sp[buf][w][lane] = s4;
            // remote slot [8+w][lane] in peer's smem
            unsigned ra = rem_sp0 + (unsigned)buf*(16*4*16);
            unsigned long long lo = pack2(s4.x, s4.y);
            unsigned long long hi = pack2(s4.z, s4.w);
            asm volatile("st.shared::cluster.b64 [%0], %1;" :: "r"(ra),     "l"(lo) : "memory");
            asm volatile("st.shared::cluster.b64 [%0], %1;" :: "r"(ra + 8), "l"(hi) : "memory");
            // local arrive: release.cta covers the local sp store
            asm volatile("mbarrier.arrive.shared.b64 _, [%0];"
                         :: "r"(loc_mb0 + (unsigned)buf*8) : "memory");
            // remote arrive: RELEASE at CLUSTER scope covers the st.shared::cluster
            // pushes (pairs with the acquire.cluster try_wait below)
            asm volatile("mbarrier.arrive.release.cluster.shared::cluster.b64 _, [%0];"
                         :: "r"(rem_mb0 + (unsigned)buf*8) : "memory");
        }

        // ---- wait for all 64 arrivals (8 local + 8 remote warps, x4 lanes) ----
        {
            unsigned mb = loc_mb0 + (unsigned)buf*8;
            asm volatile(
                "{\n\t"
                ".reg .pred P;\n"
                "W_%=:\n\t"
                "mbarrier.try_wait.parity.acquire.cluster.shared::cta.b64 P, [%0], %1, 0x989680;\n\t"
                "@!P bra W_%=;\n\t"
                "}"
                :: "r"(mb), "r"(ph) : "memory");
        }

        // ---- total scores (16 sources) + softmax + vac accumulate ----
        float4 tot = make_float4(0.f, 0.f, 0.f, 0.f);
#pragma unroll
        for (int s = 0; s < 16; s++) {
            float4 q = sp[buf][s][tq];
            tot.x += q.x; tot.y += q.y; tot.z += q.z; tot.w += q.w;
        }
        const float scale = 0.044194173824159216f;  // 1/sqrt(512)
        float4 p4;
        p4.x = __expf(tot.x * scale);
        p4.y = __expf(tot.y * scale);
        p4.z = __expf(tot.z * scale);
        p4.w = __expf(tot.w * scale);
        s_run += (p4.x + p4.y) + (p4.z + p4.w);
#pragma unroll
        for (int i = 0; i < 16; i++) {
            float a = vac[i];
            a += p4.x*x[i].x; a += p4.y*x[i].y;
            a += p4.z*x[i].z; a += p4.w*x[i].w;
            vac[i] = a;
        }
    }

    // denominator: sum over the 4 t-quads
    float stot = s_run;
    stot += __shfl_xor_sync(~0u, stot, 1);
    stot += __shfl_xor_sync(~0u, stot, 2);
    float inv = 1.0f / stot;

#pragma unroll
    for (int i = 0; i < 16; i++) {
        float t = vac[i];
        t += __shfl_xor_sync(~0u, t, 1);
        t += __shfl_xor_sync(~0u, t, 2);
        if (tq == 0) v[n*C + cbase + i*8] = t * inv;
    }

    // keep cluster alive until both CTAs are done with peer smem
    asm volatile("barrier.cluster.arrive.aligned;" ::: "memory");
    asm volatile("barrier.cluster.wait.aligned;" ::: "memory");
}

// ============ fused split-K reduce (S=4) + bias + LayerNorm ============
__global__ __launch_bounds__(256) void ln2_kernel(
    const float* __restrict__ part, const float* __restrict__ bout,
    const float* __restrict__ lnw, const float* __restrict__ lnb,
    float* __restrict__ out)
{
    __shared__ float rs[8], rss[8], bc[2];
    const int n = blockIdx.x, tid = threadIdx.x;
    const int lane = tid & 31, wid = tid >> 5;
    float x[8];
    float s = 0.f, ss = 0.f;
#pragma unroll
    for (int j = 0; j < 2; j++) {
        int cbase = j*1024 + tid*4;
        float4 a = *(const float4*)(bout + cbase);
#pragma unroll
        for (int sk = 0; sk < 4; sk++) {
            float4 p = *(const float4*)(part + (size_t)sk*Nn*C + n*C + cbase);
            a.x += p.x; a.y += p.y; a.z += p.z; a.w += p.w;
        }
        x[j*4+0]=a.x; x[j*4+1]=a.y; x[j*4+2]=a.z; x[j*4+3]=a.w;
        s  += a.x + a.y + a.z + a.w;
        ss += a.x*a.x + a.y*a.y + a.z*a.z + a.w*a.w;
    }
#pragma unroll
    for (int off = 16; off; off >>= 1) {
        s  += __shfl_xor_sync(~0u, s,  off);
        ss += __shfl_xor_sync(~0u, ss, off);
    }
    if (lane == 0) { rs[wid] = s; rss[wid] = ss; }
    __syncthreads();
    if (tid == 0) {
        float S1 = 0.f, S2 = 0.f;
#pragma unroll
        for (int i = 0; i < 8; i++) { S1 += rs[i]; S2 += rss[i]; }
        float mu = S1 * (1.0f/C);
        float var = S2 * (1.0f/C) - mu*mu;
        bc[0] = mu;
        bc[1] = rsqrtf(var + 1e-5f);
    }
    __syncthreads();
    float mu = bc[0], rstd = bc[1];
#pragma unroll
    for (int j = 0; j < 2; j++) {
        int cbase = j*1024 + tid*4;
        float4 w4 = *(const float4*)(lnw + cbase);
        float4 b4 = *(const float4*)(lnb + cbase);
        float4 o;
        o.x = (x[j*4+0]-mu)*rstd*w4.x + b4.x;
        o.y = (x[j*4+1]-mu)*rstd*w4.y + b4.y;
        o.z = (x[j*4+2]-mu)*rstd*w4.z + b4.z;
        o.w = (x[j*4+3]-mu)*rstd*w4.w + b4.w;
        *(float4*)(out + (size_t)n*C + cbase) = o;
    }
}

extern "C" void kernel_launch(void* const* d_in, const int* in_sizes, int n_in,
                              void* d_out, int out_size)
{
    const float* st_feat = (const float*)d_in[0];
    const float* lt_feat = (const float*)d_in[1];
    const float* w_st    = (const float*)d_in[2];
    const float* b_st    = (const float*)d_in[3];
    const float* w_lt    = (const float*)d_in[4];
    const float* b_lt    = (const float*)d_in[5];  (void)b_lt; // softmax-invariant
    const float* w_g     = (const float*)d_in[6];
    const float* b_g     = (const float*)d_in[7];
    const float* w_out   = (const float*)d_in[8];
    const float* b_out   = (const float*)d_in[9];
    const float* ln_w    = (const float*)d_in[10];
    const float* ln_b    = (const float*)d_in[11];
    float* out = (float*)d_out;

    float *theta, *v, *lat, *part;
    cudaGetSymbolAddress((void**)&theta, g_theta);
    cudaGetSymbolAddress((void**)&v,     g_v);
    cudaGetSymbolAddress((void**)&lat,   g_lat);
    cudaGetSymbolAddress((void**)&part,  g_part);

    // 1. theta[n,l] = st_feat @ w_st^T + b_st        [128,512]
    proj2_kernel<false><<<dim3(L/128, 2, 16), 256>>>(st_feat, w_st, part, C, L, C/16);
    reduce4_kernel<<<(Nn*L/4 + 127)/128, 128>>>(part, theta, b_st, 16, L-1, Nn*L);

    // 2. u-partials[s][n][c] = theta @ w_lt chunks   (S=4; reduce fused into attn)
    proj2_kernel<true><<<dim3(C/128, 2, 4), 256>>>(theta, w_lt, part, L, C, L/4);

    // 3. v[n,c] = lt @ softmax(u.lt / sqrt(L))       [128,2048]
    //    cluster(2): 2 CTAs per n (channel halves), 256 threads each
    attn7_kernel<<<Nn*2, 256>>>(lt_feat, part, v);

    // 4. lat[n,l] = v @ w_g^T + b_g                  [128,512]
    proj2_kernel<false><<<dim3(L/128, 2, 16), 256>>>(v, w_g, part, C, L, C/16);
    reduce4_kernel<<<(Nn*L/4 + 127)/128, 128>>>(part, lat, b_g, 16, L-1, Nn*L);

    // 5. pre-partials[s][n][c] = lat @ w_out^T chunks (S=4; reduce fused into LN)
    proj2_kernel<false><<<dim3(C/128, 2, 4), 256>>>(lat, w_out, part, L, C, L/4);

    // 6. reduce + b_out + LayerNorm -> out
    ln2_kernel<<<Nn, 256>>>(part, b_out, ln_w, ln_b, out);
}